// round 9
// baseline (speedup 1.0000x reference)
#include <cuda_runtime.h>
#include <cstdint>

#define PI_F 3.14159265358979f

__device__ __forceinline__ uint32_t f2tf32(float f) {
    uint32_t r;
    asm("cvt.rna.tf32.f32 %0, %1;" : "=r"(r) : "f"(f));
    return r;
}

__device__ __forceinline__ void mma8(float* d, const uint32_t* a, const uint32_t* b) {
    asm volatile(
        "mma.sync.aligned.m16n8k8.row.col.f32.tf32.tf32.f32 "
        "{%0,%1,%2,%3}, {%4,%5,%6,%7}, {%8,%9}, {%0,%1,%2,%3};"
        : "+f"(d[0]), "+f"(d[1]), "+f"(d[2]), "+f"(d[3])
        : "r"(a[0]), "r"(a[1]), "r"(a[2]), "r"(a[3]), "r"(b[0]), "r"(b[1]));
}

// ---------------- quantum gate helpers, 2-pixel ILP versions ----------------
__device__ __forceinline__ void gate_b5_2(const float2* G,
                                          float* a0r, float* a0i, float* a1r, float* a1i) {
    float2 g00 = G[0], g01 = G[1], g10 = G[2], g11 = G[3];
#pragma unroll
    for (int j = 0; j < 2; j++) {
        float n0r = g00.x * a0r[j] - g00.y * a0i[j] + g01.x * a1r[j] - g01.y * a1i[j];
        float n0i = g00.x * a0i[j] + g00.y * a0r[j] + g01.x * a1i[j] + g01.y * a1r[j];
        float n1r = g10.x * a0r[j] - g10.y * a0i[j] + g11.x * a1r[j] - g11.y * a1i[j];
        float n1i = g10.x * a0i[j] + g10.y * a0r[j] + g11.x * a1i[j] + g11.y * a1r[j];
        a0r[j] = n0r; a0i[j] = n0i; a1r[j] = n1r; a1i[j] = n1i;
    }
}

__device__ __forceinline__ void gate_lo_2(int bbit, int lane, const float2* G,
                                          float* a0r, float* a0i, float* a1r, float* a1i) {
    const unsigned F = 0xffffffffu;
    float2 g00 = G[0], g01 = G[1], g10 = G[2], g11 = G[3];
    int m = 1 << bbit;
    bool hi = (lane >> bbit) & 1;
    float Ar = hi ? g11.x : g00.x, Ai = hi ? g11.y : g00.y;
    float Pr = hi ? g10.x : g01.x, Pi = hi ? g10.y : g01.y;
#pragma unroll
    for (int j = 0; j < 2; j++) {
        float p0r = __shfl_xor_sync(F, a0r[j], m);
        float p0i = __shfl_xor_sync(F, a0i[j], m);
        float p1r = __shfl_xor_sync(F, a1r[j], m);
        float p1i = __shfl_xor_sync(F, a1i[j], m);
        float n0r = Ar * a0r[j] - Ai * a0i[j] + Pr * p0r - Pi * p0i;
        float n0i = Ar * a0i[j] + Ai * a0r[j] + Pr * p0i + Pi * p0r;
        float n1r = Ar * a1r[j] - Ai * a1i[j] + Pr * p1r - Pi * p1i;
        float n1i = Ar * a1i[j] + Ai * a1r[j] + Pr * p1i + Pi * p1r;
        a0r[j] = n0r; a0i[j] = n0i; a1r[j] = n1r; a1i[j] = n1i;
    }
}

__device__ __forceinline__ int ring_src(int s) {
    int b5 = (s >> 5) & 1, b4 = (s >> 4) & 1, b3 = (s >> 3) & 1;
    int b2 = (s >> 2) & 1, b1 = (s >> 1) & 1, b0 = s & 1;
    b5 ^= b0; b0 ^= b1; b1 ^= b2; b2 ^= b3; b3 ^= b4; b4 ^= b5;
    return (b5 << 5) | (b4 << 4) | (b3 << 3) | (b2 << 2) | (b1 << 1) | b0;
}

__device__ __forceinline__ void ring2_2(int q0l, int q0h, int q1l, int q1h,
                                        float* a0r, float* a0i, float* a1r, float* a1i) {
    const unsigned F = 0xffffffffu;
#pragma unroll
    for (int j = 0; j < 2; j++) {
        float x0r = __shfl_sync(F, a0r[j], q0l);
        float y0r = __shfl_sync(F, a1r[j], q0l);
        float x0i = __shfl_sync(F, a0i[j], q0l);
        float y0i = __shfl_sync(F, a1i[j], q0l);
        float x1r = __shfl_sync(F, a0r[j], q1l);
        float y1r = __shfl_sync(F, a1r[j], q1l);
        float x1i = __shfl_sync(F, a0i[j], q1l);
        float y1i = __shfl_sync(F, a1i[j], q1l);
        a0r[j] = q0h ? y0r : x0r; a0i[j] = q0h ? y0i : x0i;
        a1r[j] = q1h ? y1r : x1r; a1i[j] = q1h ? y1i : x1i;
    }
}

// ---------------- fused kernel ----------------
// 256 CTAs x 256 thr. CTA = 128 px x 72 outputs. K=576, 8 chunks of 72.
// Warps 0-3: consumers, 2 m-tiles each (mt w and mt w+4), B reuse x2.
// Warps 4-7: helpers, all staging (prefetch + STS).
// dyn smem: mainloop [xs 8448 | smB 20736]; tail reuses all as stg[128][69].
#define SMB_OFF 8448
#define FUSED_SMEM 35328

__global__ __launch_bounds__(256, 2) void k_fused(
    const float* __restrict__ x, const float* __restrict__ wr,
    const float* __restrict__ wd, const float* __restrict__ rb,
    const float* __restrict__ db, const float* __restrict__ style,
    const float* __restrict__ sw, const float* __restrict__ sb,
    const float* __restrict__ qcnn, const float* __restrict__ meas,
    const float* __restrict__ ow, const float* __restrict__ ob,
    float* __restrict__ out) {
    extern __shared__ char smem[];
    uint32_t* xs_u = (uint32_t*)smem;                  // x tile, tf32 bits, linear 2112
    char* smB = smem + SMB_OFF;                        // B frags [kt][nt][lane] uint2
    __shared__ float s_phiadd[6];
    __shared__ float s_cb0[6], s_sb0[6];
    __shared__ float2 s_g1[6][4], s_g2[6][4];
    __shared__ float sphi_all[8][96];                  // [mt][16 px][6 wires]

    const unsigned F = 0xffffffffu;
    int tid = threadIdx.x;
    int lane = tid & 31;
    int wid = tid >> 5;
    int g = lane >> 2, t4 = lane & 3;
    int px0 = blockIdx.x << 7;
    int b = px0 >> 12;
    int hwbase = px0 & 4095;
    int h0 = hwbase >> 6;             // 128 px = 2 full image rows h0, h0+1
    bool helper = (wid >= 4);
    int htid = tid - 128;             // helper-local thread id (valid when helper)

    // --- small tables ---
    if (tid < 6) {
        int i = tid;
        float b0 = qcnn[i * 6 + 3];
        s_cb0[i] = cosf(0.5f * b0);
        s_sb0[i] = sinf(0.5f * b0);
        float a1 = qcnn[36 + i * 6];
        float b1 = qcnn[36 + i * 6 + 3];
        float ca = cosf(0.5f * a1), sa = sinf(0.5f * a1);
        float cb = cosf(0.5f * b1), sbv = sinf(0.5f * b1);
        s_g1[i][0] = make_float2(cb * ca, -sbv * ca);
        s_g1[i][1] = make_float2(-cb * sa, sbv * sa);
        s_g1[i][2] = make_float2(cb * sa, sbv * sa);
        s_g1[i][3] = make_float2(cb * ca, sbv * ca);
        float th = meas[i * 3 + 0], phv = meas[i * 3 + 1], la = meas[i * 3 + 2];
        float ct = cosf(0.5f * th), st = sinf(0.5f * th);
        s_g2[i][0] = make_float2(ct, 0.f);
        s_g2[i][1] = make_float2(-cosf(la) * st, -sinf(la) * st);
        s_g2[i][2] = make_float2(cosf(phv) * st, sinf(phv) * st);
        s_g2[i][3] = make_float2(cosf(phv + la) * ct, sinf(phv + la) * ct);
    }
    if (wid < 6) {   // style projection for this batch image, wire = wid
        float4 a = reinterpret_cast<const float4*>(style + b * 128)[lane];
        float4 w = reinterpret_cast<const float4*>(sw + wid * 128)[lane];
        float acc0 = a.x * w.x + a.y * w.y + a.z * w.z + a.w * w.w;
#pragma unroll
        for (int o = 16; o; o >>= 1) acc0 += __shfl_xor_sync(F, acc0, o);
        if (lane == 0)
            s_phiadd[wid] = PI_F * tanhf(acc0 + sb[wid]) + qcnn[wid * 6];
    }

    // --- consumer A-offset table (chunk-invariant) ---
    int offs[18];
#pragma unroll
    for (int kk2 = 0; kk2 < 18; kk2++) {
        int kt = kk2 >> 1, half = kk2 & 1;
        int kloc = kt * 8 + 4 * half + t4;
        int ci = kloc / 9, kr = kloc - ci * 9;
        offs[kk2] = ci * 264 + (kr / 3) * 66 + (kr - (kr / 3) * 3);
    }
    int base0 = (wid & 3) * 16 + g;   // mt wid (row 0); mt wid+4 = base0 + 66

    float acc[2][9][4];
#pragma unroll
    for (int m = 0; m < 2; m++)
#pragma unroll
        for (int j = 0; j < 9; j++)
#pragma unroll
            for (int c = 0; c < 4; c++) acc[m][j][c] = 0.f;

    float px_x[17];
    float4 px_w[10];

    // --- helper prefetch chunk 0 ---
    if (helper) {
#pragma unroll
        for (int it = 0; it < 17; it++) {
            int j = htid + (it << 7);
            float v = 0.f;
            if (j < 2112) {
                int ci = j / 264, rem = j - ci * 264;
                int r = rem / 66, cpos = rem - r * 66;
                int gh = h0 - 1 + r, gw = cpos - 1;
                if ((unsigned)gh < 64u && (unsigned)gw < 64u)
                    v = __ldg(x + (((b << 6) + ci) << 12) + (gh << 6) + gw);
            }
            px_x[it] = v;
        }
#pragma unroll
        for (int it = 0; it < 10; it++) {
            int j = htid + (it << 7);
            if (j < 1260) {
                int n = j / 18, qf = j - n * 18;
                const float* src = (n < 64) ? (wr + n * 576) : (wd + (n - 64) * 576);
                px_w[it] = *reinterpret_cast<const float4*>(src + (qf << 2));
            }
        }
    }

    // --- pipelined mainloop ---
    for (int chunk = 0; chunk < 8; chunk++) {
        if (chunk) __syncthreads();           // prev mma done reading smem
        if (helper) {
            // STS staged regs (cvt at store)
#pragma unroll
            for (int it = 0; it < 17; it++) {
                int j = htid + (it << 7);
                if (j < 2112) xs_u[j] = f2tf32(px_x[it]);
            }
#pragma unroll
            for (int it = 0; it < 10; it++) {
                int j = htid + (it << 7);
                if (j < 1260) {
                    int n = j / 18, qf = j - n * 18;
                    int kt = qf >> 1, half = qf & 1;
                    uint32_t* dst = reinterpret_cast<uint32_t*>(smB) +
                                    (((kt * 9 + (n >> 3)) * 32 + ((n & 7) << 2)) << 1) + half;
                    dst[0] = f2tf32(px_w[it].x);
                    dst[2] = f2tf32(px_w[it].y);
                    dst[4] = f2tf32(px_w[it].z);
                    dst[6] = f2tf32(px_w[it].w);
                }
            }
        }
        __syncthreads();
        if (helper) {
            // prefetch next chunk (LDG overlaps consumers' mma)
            if (chunk < 7) {
                int cn = chunk + 1;
#pragma unroll
                for (int it = 0; it < 17; it++) {
                    int j = htid + (it << 7);
                    float v = 0.f;
                    if (j < 2112) {
                        int ci = j / 264, rem = j - ci * 264;
                        int r = rem / 66, cpos = rem - r * 66;
                        int gh = h0 - 1 + r, gw = cpos - 1;
                        if ((unsigned)gh < 64u && (unsigned)gw < 64u)
                            v = __ldg(x + (((b << 6) + (cn << 3) + ci) << 12) + (gh << 6) + gw);
                    }
                    px_x[it] = v;
                }
#pragma unroll
                for (int it = 0; it < 10; it++) {
                    int j = htid + (it << 7);
                    if (j < 1260) {
                        int n = j / 18, qf = j - n * 18;
                        const float* src = (n < 64) ? (wr + n * 576) : (wd + (n - 64) * 576);
                        px_w[it] = *reinterpret_cast<const float4*>(src + cn * 72 + (qf << 2));
                    }
                }
            }
        } else {
            // consumer mma: 2 m-tiles per warp, B loaded once per (kt, nt)
#pragma unroll
            for (int kt = 0; kt < 9; kt++) {
                uint32_t A0[4], A1[4];
                A0[0] = xs_u[offs[2 * kt] + base0];
                A0[1] = xs_u[offs[2 * kt] + base0 + 8];
                A0[2] = xs_u[offs[2 * kt + 1] + base0];
                A0[3] = xs_u[offs[2 * kt + 1] + base0 + 8];
                A1[0] = xs_u[offs[2 * kt] + base0 + 66];
                A1[1] = xs_u[offs[2 * kt] + base0 + 74];
                A1[2] = xs_u[offs[2 * kt + 1] + base0 + 66];
                A1[3] = xs_u[offs[2 * kt + 1] + base0 + 74];
#pragma unroll
                for (int nt = 0; nt < 9; nt++) {
                    uint2 bb = *reinterpret_cast<const uint2*>(
                        smB + ((kt * 9 + nt) * 32 + lane) * 8);
                    uint32_t B[2] = {bb.x, bb.y};
                    mma8(acc[0][nt], A0, B);
                    mma8(acc[1][nt], A1, B);
                }
            }
        }
    }
    __syncthreads();   // mma done; dyn smem free for tail scratch

    float* stg = (float*)smem;                   // [128 px][69] floats

    // --- phase 1 (consumers): phi staging + conv epilogue for both m-tiles ---
    if (!helper) {
#pragma unroll
        for (int m = 0; m < 2; m++) {
            int mt = (wid & 3) + 4 * m;
            float* sphi = sphi_all[mt];
            if (t4 < 3) {
#pragma unroll
                for (int c = 0; c < 4; c++) {
                    int pxl = g + 8 * (c >> 1);
                    int wire = 2 * t4 + (c & 1);
                    sphi[pxl * 6 + wire] =
                        PI_F * tanhf(acc[m][8][c] + __ldg(db + wire)) + s_phiadd[wire];
                }
            }
#pragma unroll
            for (int nt = 0; nt < 8; nt++) {
#pragma unroll
                for (int c = 0; c < 4; c++) {
                    int pxl = g + 8 * (c >> 1);
                    int co = nt * 8 + 2 * t4 + (c & 1);
                    stg[(mt * 16 + pxl) * 69 + co] = acc[m][nt][c] + __ldg(rb + co);
                }
            }
        }
    }
    __syncthreads();

    // --- phase 2 (all 8 warps): circuit, 2 pixels in flight, mt = wid ---
    float* sphi = sphi_all[wid];
    int q0 = ring_src(lane), q1 = ring_src(lane + 32);
    int q0l = q0 & 31, q0h = q0 >> 5;
    int q1l = q1 & 31, q1h = q1 >> 5;
    float obr0 = __ldg(ob + lane), obr1 = __ldg(ob + lane + 32);
    float owA[6], owB[6];
#pragma unroll
    for (int i = 0; i < 6; i++) {
        owA[i] = __ldg(ow + lane * 6 + i);
        owB[i] = __ldg(ow + (lane + 32) * 6 + i);
    }

    for (int pp = 0; pp < 8; pp++) {
        float phiA = (lane < 6) ? sphi[pp * 6 + lane] : 0.f;
        float phiB = (lane < 6) ? sphi[(pp + 8) * 6 + lane] : 0.f;
        float svv[2], cvv[2];
        __sincosf(0.5f * phiA, &svv[0], &cvv[0]);
        __sincosf(0.5f * phiB, &svv[1], &cvv[1]);

        float a0r[2] = {1.f, 1.f}, a0i[2] = {0.f, 0.f};
        float a1r[2] = {1.f, 1.f}, a1i[2] = {0.f, 0.f};
#pragma unroll
        for (int i = 0; i < 6; i++) {
            float cb = s_cb0[i], sbv = s_sb0[i];
            int bit = (lane >> (5 - i)) & 1;
#pragma unroll
            for (int j = 0; j < 2; j++) {
                float cv = __shfl_sync(F, cvv[j], i);
                float sv = __shfl_sync(F, svv[j], i);
                float u0r = cv * cb, u0i = -cv * sbv;
                float u1r = sv * cb, u1i = sv * sbv;
                float ur0 = bit ? u1r : u0r, ui0 = bit ? u1i : u0i;
                float ur1 = (i == 0) ? u1r : ur0, ui1 = (i == 0) ? u1i : ui0;
                float nr = a0r[j] * ur0 - a0i[j] * ui0;
                float ni = a0r[j] * ui0 + a0i[j] * ur0;
                a0r[j] = nr; a0i[j] = ni;
                nr = a1r[j] * ur1 - a1i[j] * ui1;
                ni = a1r[j] * ui1 + a1i[j] * ur1;
                a1r[j] = nr; a1i[j] = ni;
            }
        }

        ring2_2(q0l, q0h, q1l, q1h, a0r, a0i, a1r, a1i);
#pragma unroll
        for (int i = 0; i < 6; i++) {
            if (i == 0) gate_b5_2(s_g1[0], a0r, a0i, a1r, a1i);
            else        gate_lo_2(5 - i, lane, s_g1[i], a0r, a0i, a1r, a1i);
        }
        ring2_2(q0l, q0h, q1l, q1h, a0r, a0i, a1r, a1i);
#pragma unroll
        for (int i = 0; i < 6; i++) {
            if (i == 0) gate_b5_2(s_g2[0], a0r, a0i, a1r, a1i);
            else        gate_lo_2(5 - i, lane, s_g2[i], a0r, a0i, a1r, a1i);
        }

#pragma unroll
        for (int j = 0; j < 2; j++) {
            float p0 = a0r[j] * a0r[j] + a0i[j] * a0i[j];
            float p1 = a1r[j] * a1r[j] + a1i[j] * a1i[j];
            float t0 = p0 + p1, dd = p0 - p1;
#pragma unroll
            for (int m = 16; m; m >>= 1) dd += __shfl_xor_sync(F, dd, m);
#pragma unroll
            for (int m = 16; m; m >>= 1) {
                float o = __shfl_xor_sync(F, t0, m);
                t0 = ((lane & m) ? -t0 : t0) + o;
            }
            float e1 = __shfl_sync(F, t0, 16);
            float e2 = __shfl_sync(F, t0, 8);
            float e3 = __shfl_sync(F, t0, 4);
            float e4 = __shfl_sync(F, t0, 2);
            float e5 = __shfl_sync(F, t0, 1);

            float o0 = fmaf(owA[0], dd, obr0);
            float o1 = fmaf(owB[0], dd, obr1);
            o0 = fmaf(owA[1], e1, o0); o1 = fmaf(owB[1], e1, o1);
            o0 = fmaf(owA[2], e2, o0); o1 = fmaf(owB[2], e2, o1);
            o0 = fmaf(owA[3], e3, o0); o1 = fmaf(owB[3], e3, o1);
            o0 = fmaf(owA[4], e4, o0); o1 = fmaf(owB[4], e4, o1);
            o0 = fmaf(owA[5], e5, o0); o1 = fmaf(owB[5], e5, o1);

            int px = wid * 16 + pp + 8 * j;
            stg[px * 69 + lane] += o0;
            stg[px * 69 + lane + 32] += o1;
        }
    }
    __syncthreads();

    // --- fully coalesced final write: 64 co rows x 128 contiguous px ---
    for (int i = tid; i < 8192; i += 256) {
        int co = i >> 7, px = i & 127;
        out[(((b << 6) + co) << 12) + hwbase + px] = stg[px * 69 + co];
    }
}

// ---------------- launch ----------------
extern "C" void kernel_launch(void* const* d_in, const int* in_sizes, int n_in,
                              void* d_out, int out_size) {
    const float* x     = (const float*)d_in[0];
    const float* style = (const float*)d_in[1];
    const float* wd    = (const float*)d_in[2];   // data_proj_w [6,576]
    const float* db    = (const float*)d_in[3];   // data_proj_b [6]
    const float* sw    = (const float*)d_in[4];   // style_to_data_w [6,128]
    const float* sb    = (const float*)d_in[5];   // style_to_data_b [6]
    const float* qcnn  = (const float*)d_in[6];   // [2,6,2,3]
    const float* meas  = (const float*)d_in[7];   // [6,3]
    const float* ow    = (const float*)d_in[8];   // out_proj_w [64,6]
    const float* ob    = (const float*)d_in[9];   // out_proj_b [64]
    const float* wr    = (const float*)d_in[10];  // res_proj_w [64,576]
    const float* rb    = (const float*)d_in[11];  // res_proj_b [64]
    float* out = (float*)d_out;

    cudaFuncSetAttribute(k_fused, cudaFuncAttributeMaxDynamicSharedMemorySize, FUSED_SMEM);
    k_fused<<<256, 256, FUSED_SMEM>>>(x, wr, wd, rb, db, style, sw, sb,
                                      qcnn, meas, ow, ob, out);
}

// round 10
// speedup vs baseline: 1.2521x; 1.2521x over previous
#include <cuda_runtime.h>
#include <cstdint>

#define PI_F 3.14159265358979f

// ---------------- device-global tables (prep -> main) ----------------
__device__ float d_B1f[8192];   // B1[64k][128n] in mma B-frag layout, tf32
__device__ float d_Wqf[4096];   // Wq'[64k][64n] in mma B-frag layout, tf32

__device__ __forceinline__ uint32_t f2tf32(float f) {
    uint32_t r;
    asm("cvt.rna.tf32.f32 %0, %1;" : "=r"(r) : "f"(f));
    return r;
}

__device__ __forceinline__ void mma8(float* d, const uint32_t* a, const uint32_t* b) {
    asm volatile(
        "mma.sync.aligned.m16n8k8.row.col.f32.tf32.tf32.f32 "
        "{%0,%1,%2,%3}, {%4,%5,%6,%7}, {%8,%9}, {%0,%1,%2,%3};"
        : "+f"(d[0]), "+f"(d[1]), "+f"(d[2]), "+f"(d[3])
        : "r"(a[0]), "r"(a[1]), "r"(a[2]), "r"(a[3]), "r"(b[0]), "r"(b[1]));
}

// B-fragment storage index (float units) for element (k, n)
__device__ __forceinline__ int fidxB1(int k, int n) {   // 16 n-tiles
    return ((((k >> 3) * 16 + (n >> 3)) * 32 + (n & 7) * 4 + (k & 3)) << 1) + ((k >> 2) & 1);
}
__device__ __forceinline__ int fidxWq(int k, int n) {   // 8 n-tiles
    return ((((k >> 3) * 8 + (n >> 3)) * 32 + (n & 7) * 4 + (k & 3)) << 1) + ((k >> 2) & 1);
}

// ---------------- quantum gate helpers (2-state ILP, used by prep) ----------------
__device__ __forceinline__ void gate_b5_2(const float2* G,
                                          float* a0r, float* a0i, float* a1r, float* a1i) {
    float2 g00 = G[0], g01 = G[1], g10 = G[2], g11 = G[3];
#pragma unroll
    for (int j = 0; j < 2; j++) {
        float n0r = g00.x * a0r[j] - g00.y * a0i[j] + g01.x * a1r[j] - g01.y * a1i[j];
        float n0i = g00.x * a0i[j] + g00.y * a0r[j] + g01.x * a1i[j] + g01.y * a1r[j];
        float n1r = g10.x * a0r[j] - g10.y * a0i[j] + g11.x * a1r[j] - g11.y * a1i[j];
        float n1i = g10.x * a0i[j] + g10.y * a0r[j] + g11.x * a1i[j] + g11.y * a1r[j];
        a0r[j] = n0r; a0i[j] = n0i; a1r[j] = n1r; a1i[j] = n1i;
    }
}

__device__ __forceinline__ void gate_lo_2(int bbit, int lane, const float2* G,
                                          float* a0r, float* a0i, float* a1r, float* a1i) {
    const unsigned F = 0xffffffffu;
    float2 g00 = G[0], g01 = G[1], g10 = G[2], g11 = G[3];
    int m = 1 << bbit;
    bool hi = (lane >> bbit) & 1;
    float Ar = hi ? g11.x : g00.x, Ai = hi ? g11.y : g00.y;
    float Pr = hi ? g10.x : g01.x, Pi = hi ? g10.y : g01.y;
#pragma unroll
    for (int j = 0; j < 2; j++) {
        float p0r = __shfl_xor_sync(F, a0r[j], m);
        float p0i = __shfl_xor_sync(F, a0i[j], m);
        float p1r = __shfl_xor_sync(F, a1r[j], m);
        float p1i = __shfl_xor_sync(F, a1i[j], m);
        float n0r = Ar * a0r[j] - Ai * a0i[j] + Pr * p0r - Pi * p0i;
        float n0i = Ar * a0i[j] + Ai * a0r[j] + Pr * p0i + Pi * p0r;
        float n1r = Ar * a1r[j] - Ai * a1i[j] + Pr * p1r - Pi * p1i;
        float n1i = Ar * a1i[j] + Ai * a1r[j] + Pr * p1i + Pi * p1r;
        a0r[j] = n0r; a0i[j] = n0i; a1r[j] = n1r; a1i[j] = n1i;
    }
}

__device__ __forceinline__ int ring_src(int s) {
    int b5 = (s >> 5) & 1, b4 = (s >> 4) & 1, b3 = (s >> 3) & 1;
    int b2 = (s >> 2) & 1, b1 = (s >> 1) & 1, b0 = s & 1;
    b5 ^= b0; b0 ^= b1; b1 ^= b2; b2 ^= b3; b3 ^= b4; b4 ^= b5;
    return (b5 << 5) | (b4 << 4) | (b3 << 3) | (b2 << 2) | (b1 << 1) | b0;
}

__device__ __forceinline__ void ring2_2(int q0l, int q0h, int q1l, int q1h,
                                        float* a0r, float* a0i, float* a1r, float* a1i) {
    const unsigned F = 0xffffffffu;
#pragma unroll
    for (int j = 0; j < 2; j++) {
        float x0r = __shfl_sync(F, a0r[j], q0l);
        float y0r = __shfl_sync(F, a1r[j], q0l);
        float x0i = __shfl_sync(F, a0i[j], q0l);
        float y0i = __shfl_sync(F, a1i[j], q0l);
        float x1r = __shfl_sync(F, a0r[j], q1l);
        float y1r = __shfl_sync(F, a1r[j], q1l);
        float x1i = __shfl_sync(F, a0i[j], q1l);
        float y1i = __shfl_sync(F, a1i[j], q1l);
        a0r[j] = q0h ? y0r : x0r; a0i[j] = q0h ? y0i : x0i;
        a1r[j] = q1h ? y1r : x1r; a1i[j] = q1h ? y1i : x1i;
    }
}

// ---------------- prep: build B1 (fixed circuit unitary) + Wq' fragments ----------------
__global__ void k_prep(const float* __restrict__ qcnn, const float* __restrict__ meas,
                       const float* __restrict__ ow) {
    __shared__ float2 s_g1[6][4], s_g2[6][4];
    __shared__ float s_b0[6];
    int tid = threadIdx.x, lane = tid & 31, warp = tid >> 5;

    if (tid < 6) {
        int i = tid;
        float b0 = qcnn[i * 6 + 3];
        s_b0[i] = b0;
        float a1 = qcnn[36 + i * 6];
        float b1 = qcnn[36 + i * 6 + 3];
        float ca = cosf(0.5f * a1), sa = sinf(0.5f * a1);
        float cb = cosf(0.5f * b1), sbv = sinf(0.5f * b1);
        s_g1[i][0] = make_float2(cb * ca, -sbv * ca);
        s_g1[i][1] = make_float2(-cb * sa, sbv * sa);
        s_g1[i][2] = make_float2(cb * sa, sbv * sa);
        s_g1[i][3] = make_float2(cb * ca, sbv * ca);
        float th = meas[i * 3 + 0], phv = meas[i * 3 + 1], la = meas[i * 3 + 2];
        float ct = cosf(0.5f * th), st = sinf(0.5f * th);
        s_g2[i][0] = make_float2(ct, 0.f);
        s_g2[i][1] = make_float2(-cosf(la) * st, -sinf(la) * st);
        s_g2[i][2] = make_float2(cosf(phv) * st, sinf(phv) * st);
        s_g2[i][3] = make_float2(cosf(phv + la) * ct, sinf(phv + la) * ct);
    }
    __syncthreads();

    int q0 = ring_src(lane), q1 = ring_src(lane + 32);
    int q0l = q0 & 31, q0h = q0 >> 5;
    int q1l = q1 & 31, q1h = q1 >> 5;

    // simulate 64 basis columns (with folded per-qubit phases), 2 per pass
    for (int q = 0; q < 4; q++) {
        int tcol[2] = {(warp * 4 + q) * 2, (warp * 4 + q) * 2 + 1};
        float a0r[2], a0i[2], a1r[2], a1i[2];
#pragma unroll
        for (int j = 0; j < 2; j++) {
            float th = 0.f;
#pragma unroll
            for (int i = 0; i < 6; i++)
                if ((tcol[j] >> (5 - i)) & 1) th += s_b0[i];
            float sv, cv;
            __sincosf(th, &sv, &cv);
            a0r[j] = (lane == tcol[j]) ? cv : 0.f;
            a0i[j] = (lane == tcol[j]) ? sv : 0.f;
            a1r[j] = (lane + 32 == tcol[j]) ? cv : 0.f;
            a1i[j] = (lane + 32 == tcol[j]) ? sv : 0.f;
        }
        ring2_2(q0l, q0h, q1l, q1h, a0r, a0i, a1r, a1i);
#pragma unroll
        for (int i = 0; i < 6; i++) {
            if (i == 0) gate_b5_2(s_g1[0], a0r, a0i, a1r, a1i);
            else        gate_lo_2(5 - i, lane, s_g1[i], a0r, a0i, a1r, a1i);
        }
        ring2_2(q0l, q0h, q1l, q1h, a0r, a0i, a1r, a1i);
#pragma unroll
        for (int i = 0; i < 6; i++) {
            if (i == 0) gate_b5_2(s_g2[0], a0r, a0i, a1r, a1i);
            else        gate_lo_2(5 - i, lane, s_g2[i], a0r, a0i, a1r, a1i);
        }
#pragma unroll
        for (int j = 0; j < 2; j++) {
            int k = tcol[j];
            d_B1f[fidxB1(k, lane)]          = __uint_as_float(f2tf32(a0r[j]));
            d_B1f[fidxB1(k, 64 + lane)]     = __uint_as_float(f2tf32(a0i[j]));
            d_B1f[fidxB1(k, lane + 32)]     = __uint_as_float(f2tf32(a1r[j]));
            d_B1f[fidxB1(k, 96 + lane)]     = __uint_as_float(f2tf32(a1i[j]));
        }
    }
    // Wq'[s][co] = sum_i ow[co,i]*sign_i(s)
    for (int i = tid; i < 4096; i += 256) {
        int s = i >> 6, co = i & 63;
        float acc = 0.f;
#pragma unroll
        for (int w = 0; w < 6; w++)
            acc += ow[co * 6 + w] * (((s >> (5 - w)) & 1) ? -1.f : 1.f);
        d_Wqf[fidxWq(s, co)] = __uint_as_float(f2tf32(acc));
    }
}

// ---------------- fused kernel ----------------
// Mainloop identical to R8 (proven). Tail: real product state -> GEMM1 (B1) ->
// probs -> GEMM2 (Wq') -> merge with conv -> coalesced write.
// dyn smem: mainloop [xs 8448 | smB 20736] (<= 33280);
// tail: [stg 33280 (overlays mainloop) | PSI 33280 | B1s 32768 (Wq overlays)]
#define SMB_OFF 8448
#define PSI_OFF 33280
#define B1_OFF  66560
#define FUSED_SMEM 99328

__global__ __launch_bounds__(256, 2) void k_fused(
    const float* __restrict__ x, const float* __restrict__ wr,
    const float* __restrict__ wd, const float* __restrict__ rb,
    const float* __restrict__ db, const float* __restrict__ style,
    const float* __restrict__ sw, const float* __restrict__ sb,
    const float* __restrict__ qcnn, const float* __restrict__ ob,
    float* __restrict__ out) {
    extern __shared__ char smem[];
    uint32_t* xs_u = (uint32_t*)smem;                  // x tile, tf32 bits, linear 2112
    char* smB = smem + SMB_OFF;                        // B frags [kt][nt][lane] uint2
    __shared__ float s_phiadd[6];
    __shared__ float2 scs[8][96];                      // [warp][px*6+wire] (cos,sin)
    __shared__ float sphi_all[8][96];                  // [warp][16 px][6 wires]

    const unsigned F = 0xffffffffu;
    int tid = threadIdx.x;
    int lane = tid & 31;
    int wid = tid >> 5;               // warp = m-tile
    int g = lane >> 2, t4 = lane & 3;
    int px0 = blockIdx.x << 7;
    int b = px0 >> 12;
    int hwbase = px0 & 4095;
    int h0 = hwbase >> 6;

    if (wid < 6) {   // style projection, wire = wid
        float4 a = reinterpret_cast<const float4*>(style + b * 128)[lane];
        float4 w = reinterpret_cast<const float4*>(sw + wid * 128)[lane];
        float acc0 = a.x * w.x + a.y * w.y + a.z * w.z + a.w * w.w;
#pragma unroll
        for (int o = 16; o; o >>= 1) acc0 += __shfl_xor_sync(F, acc0, o);
        if (lane == 0)
            s_phiadd[wid] = PI_F * tanhf(acc0 + sb[wid]) + qcnn[wid * 6];
    }

    // --- A-offset table (chunk-invariant) ---
    int offs[18];
#pragma unroll
    for (int kk2 = 0; kk2 < 18; kk2++) {
        int kt = kk2 >> 1, half = kk2 & 1;
        int kloc = kt * 8 + 4 * half + t4;
        int ci = kloc / 9, kr = kloc - ci * 9;
        offs[kk2] = ci * 264 + (kr / 3) * 66 + (kr - (kr / 3) * 3);
    }
    int base0 = (wid >> 2) * 66 + (wid & 3) * 16 + g;

    float acc[9][4];
#pragma unroll
    for (int j = 0; j < 9; j++)
#pragma unroll
        for (int c = 0; c < 4; c++) acc[j][c] = 0.f;

    float px_x[9];
    float4 px_w[5];

    // --- prefetch chunk 0 ---
#pragma unroll
    for (int it = 0; it < 9; it++) {
        int j = tid + (it << 8);
        float v = 0.f;
        if (it < 8 || tid < 64) {
            int ci = j / 264, rem = j - ci * 264;
            int r = rem / 66, cpos = rem - r * 66;
            int gh = h0 - 1 + r, gw = cpos - 1;
            if ((unsigned)gh < 64u && (unsigned)gw < 64u)
                v = __ldg(x + (((b << 6) + ci) << 12) + (gh << 6) + gw);
        }
        px_x[it] = v;
    }
#pragma unroll
    for (int it = 0; it < 5; it++) {
        if (it < 4 || tid < 236) {
            int j = tid + (it << 8);
            int n = j / 18, qf = j - n * 18;
            const float* src = (n < 64) ? (wr + n * 576) : (wd + (n - 64) * 576);
            px_w[it] = *reinterpret_cast<const float4*>(src + (qf << 2));
        }
    }

    // --- pipelined mainloop (R8) ---
    for (int chunk = 0; chunk < 8; chunk++) {
        if (chunk) __syncthreads();
#pragma unroll
        for (int it = 0; it < 9; it++) {
            if (it < 8 || tid < 64)
                xs_u[tid + (it << 8)] = f2tf32(px_x[it]);
        }
#pragma unroll
        for (int it = 0; it < 5; it++) {
            if (it < 4 || tid < 236) {
                int j = tid + (it << 8);
                int n = j / 18, qf = j - n * 18;
                int kt = qf >> 1, half = qf & 1;
                uint32_t* dst = reinterpret_cast<uint32_t*>(smB) +
                                (((kt * 9 + (n >> 3)) * 32 + ((n & 7) << 2)) << 1) + half;
                dst[0] = f2tf32(px_w[it].x);
                dst[2] = f2tf32(px_w[it].y);
                dst[4] = f2tf32(px_w[it].z);
                dst[6] = f2tf32(px_w[it].w);
            }
        }
        __syncthreads();
        if (chunk < 7) {
            int cn = chunk + 1;
#pragma unroll
            for (int it = 0; it < 9; it++) {
                int j = tid + (it << 8);
                float v = 0.f;
                if (it < 8 || tid < 64) {
                    int ci = j / 264, rem = j - ci * 264;
                    int r = rem / 66, cpos = rem - r * 66;
                    int gh = h0 - 1 + r, gw = cpos - 1;
                    if ((unsigned)gh < 64u && (unsigned)gw < 64u)
                        v = __ldg(x + (((b << 6) + (cn << 3) + ci) << 12) + (gh << 6) + gw);
                }
                px_x[it] = v;
            }
#pragma unroll
            for (int it = 0; it < 5; it++) {
                if (it < 4 || tid < 236) {
                    int j = tid + (it << 8);
                    int n = j / 18, qf = j - n * 18;
                    const float* src = (n < 64) ? (wr + n * 576) : (wd + (n - 64) * 576);
                    px_w[it] = *reinterpret_cast<const float4*>(src + cn * 72 + (qf << 2));
                }
            }
        }
#pragma unroll
        for (int kt = 0; kt < 9; kt++) {
            uint32_t A[4];
            A[0] = xs_u[offs[2 * kt] + base0];
            A[1] = xs_u[offs[2 * kt] + base0 + 8];
            A[2] = xs_u[offs[2 * kt + 1] + base0];
            A[3] = xs_u[offs[2 * kt + 1] + base0 + 8];
#pragma unroll
            for (int nt = 0; nt < 9; nt++) {
                uint2 bb = *reinterpret_cast<const uint2*>(
                    smB + ((kt * 9 + nt) * 32 + lane) * 8);
                uint32_t B[2] = {bb.x, bb.y};
                mma8(acc[nt], A, B);
            }
        }
    }
    __syncthreads();   // mma done; mainloop smem regions reusable

    float* stg = (float*)smem;                         // [128][65]
    float* PSI = (float*)(smem + PSI_OFF);             // [128][65]
    uint32_t* PSIu = (uint32_t*)PSI;
    char* B1s = smem + B1_OFF;

    // --- stage B1 fragments into smem (L2-resident, 32KB) ---
    {
        const float4* src = (const float4*)d_B1f;
        float4* dst = (float4*)B1s;
        for (int i = tid; i < 2048; i += 256) dst[i] = src[i];
    }

    // --- phi -> sphi ; conv epilogue -> stg ---
    float* sphi = sphi_all[wid];
    if (t4 < 3) {
#pragma unroll
        for (int c = 0; c < 4; c++) {
            int pxl = g + 8 * (c >> 1);
            int wire = 2 * t4 + (c & 1);
            sphi[pxl * 6 + wire] =
                PI_F * tanhf(acc[8][c] + __ldg(db + wire)) + s_phiadd[wire];
        }
    }
#pragma unroll
    for (int nt = 0; nt < 8; nt++) {
#pragma unroll
        for (int c = 0; c < 4; c++) {
            int pxl = g + 8 * (c >> 1);
            int co = nt * 8 + 2 * t4 + (c & 1);
            stg[(wid * 16 + pxl) * 65 + co] = acc[nt][c] + __ldg(rb + co);
        }
    }
    __syncwarp();

    // --- cos/sin(phi/2) per (px, wire): 3 sincos per lane ---
#pragma unroll
    for (int r = 0; r < 3; r++) {
        int idx = lane + (r << 5);
        float ph = sphi[idx];      // idx = pxl*6+wire, 96 values
        float sv, cv;
        __sincosf(0.5f * ph, &sv, &cv);
        scs[wid][idx] = make_float2(cv, sv);
    }
    __syncwarp();

    // --- build real product state PSI[px][64] (tf32 bits) ---
    for (int pxl = 0; pxl < 16; pxl++) {
        float2 c0 = scs[wid][pxl * 6 + 0];
        float m = 1.f;
#pragma unroll
        for (int i = 1; i < 6; i++) {
            float2 ci = scs[wid][pxl * 6 + i];
            m *= ((lane >> (5 - i)) & 1) ? ci.y : ci.x;
        }
        int row = (wid * 16 + pxl) * 65;
        PSIu[row + lane] = f2tf32(c0.x * m);
        PSIu[row + lane + 32] = f2tf32(c0.y * m);
    }
    __syncthreads();   // B1s + all PSI ready (PSI only warp-local, B1s global)

    // --- GEMM1: D1[px][128] = PSI[px][64] x B1 ---
    float acc1[16][4];
#pragma unroll
    for (int j = 0; j < 16; j++)
#pragma unroll
        for (int c = 0; c < 4; c++) acc1[j][c] = 0.f;
    {
        int abase = (wid * 16 + g) * 65 + t4;
#pragma unroll
        for (int kt = 0; kt < 8; kt++) {
            uint32_t A[4];
            A[0] = PSIu[abase + kt * 8];
            A[1] = PSIu[abase + kt * 8 + 8 * 65];
            A[2] = PSIu[abase + kt * 8 + 4];
            A[3] = PSIu[abase + kt * 8 + 4 + 8 * 65];
#pragma unroll
            for (int nt = 0; nt < 16; nt++) {
                uint2 bb = *reinterpret_cast<const uint2*>(
                    B1s + ((kt * 16 + nt) * 32 + lane) * 8);
                uint32_t B[2] = {bb.x, bb.y};
                mma8(acc1[nt], A, B);
            }
        }
    }
    // --- probs into PSI region (own rows only) ---
#pragma unroll
    for (int nt = 0; nt < 8; nt++) {
#pragma unroll
        for (int c = 0; c < 4; c++) {
            float p = acc1[nt][c] * acc1[nt][c] + acc1[nt + 8][c] * acc1[nt + 8][c];
            int s = nt * 8 + 2 * t4 + (c & 1);
            int pxg = wid * 16 + g + 8 * (c >> 1);
            PSIu[pxg * 65 + s] = f2tf32(p);
        }
    }
    __syncthreads();   // all GEMM1 B-reads done -> reuse B1s for Wq
    {
        const float4* src = (const float4*)d_Wqf;
        float4* dst = (float4*)B1s;
        for (int i = tid; i < 1024; i += 256) dst[i] = src[i];
    }
    __syncthreads();

    // --- GEMM2: D2[px][64co] = p[px][64] x Wq' ---
    float acc2[8][4];
#pragma unroll
    for (int j = 0; j < 8; j++)
#pragma unroll
        for (int c = 0; c < 4; c++) acc2[j][c] = 0.f;
    {
        int abase = (wid * 16 + g) * 65 + t4;
#pragma unroll
        for (int kt = 0; kt < 8; kt++) {
            uint32_t A[4];
            A[0] = PSIu[abase + kt * 8];
            A[1] = PSIu[abase + kt * 8 + 8 * 65];
            A[2] = PSIu[abase + kt * 8 + 4];
            A[3] = PSIu[abase + kt * 8 + 4 + 8 * 65];
#pragma unroll
            for (int nt = 0; nt < 8; nt++) {
                uint2 bb = *reinterpret_cast<const uint2*>(
                    B1s + ((kt * 8 + nt) * 32 + lane) * 8);
                uint32_t B[2] = {bb.x, bb.y};
                mma8(acc2[nt], A, B);
            }
        }
    }
    // --- merge quant output + bias into stg ---
#pragma unroll
    for (int nt = 0; nt < 8; nt++) {
#pragma unroll
        for (int c = 0; c < 4; c++) {
            int co = nt * 8 + 2 * t4 + (c & 1);
            int pxg = wid * 16 + g + 8 * (c >> 1);
            stg[pxg * 65 + co] += acc2[nt][c] + __ldg(ob + co);
        }
    }
    __syncthreads();

    // --- fully coalesced final write ---
    for (int i = tid; i < 8192; i += 256) {
        int co = i >> 7, px = i & 127;
        out[(((b << 6) + co) << 12) + hwbase + px] = stg[px * 65 + co];
    }
}

// ---------------- launch ----------------
extern "C" void kernel_launch(void* const* d_in, const int* in_sizes, int n_in,
                              void* d_out, int out_size) {
    const float* x     = (const float*)d_in[0];
    const float* style = (const float*)d_in[1];
    const float* wd    = (const float*)d_in[2];   // data_proj_w [6,576]
    const float* db    = (const float*)d_in[3];   // data_proj_b [6]
    const float* sw    = (const float*)d_in[4];   // style_to_data_w [6,128]
    const float* sb    = (const float*)d_in[5];   // style_to_data_b [6]
    const float* qcnn  = (const float*)d_in[6];   // [2,6,2,3]
    const float* meas  = (const float*)d_in[7];   // [6,3]
    const float* ow    = (const float*)d_in[8];   // out_proj_w [64,6]
    const float* ob    = (const float*)d_in[9];   // out_proj_b [64]
    const float* wr    = (const float*)d_in[10];  // res_proj_w [64,576]
    const float* rb    = (const float*)d_in[11];  // res_proj_b [64]
    float* out = (float*)d_out;

    cudaFuncSetAttribute(k_fused, cudaFuncAttributeMaxDynamicSharedMemorySize, FUSED_SMEM);
    k_prep<<<1, 256>>>(qcnn, meas, ow);
    k_fused<<<256, 256, FUSED_SMEM>>>(x, wr, wd, rb, db, style, sw, sb,
                                      qcnn, ob, out);
}